// round 16
// baseline (speedup 1.0000x reference)
#include <cuda_runtime.h>
#include <cuda_fp16.h>
#include <mma.h>
#include <math.h>
#include <stdint.h>

using namespace nvcuda;

#define N_EXPERTS 8
#define TOPK      2
#define IN_DIM    512
#define HID_DIM   1024
#define OUT_DIM   512
#define NTOK      16384

#define TILE_M 128
#define TILE_N 256
#define NTHREADS 512
#define MAX_TILES ((NTOK * TOPK) / TILE_M + N_EXPERTS)   // 264
#define PADDED    (MAX_TILES * TILE_M)                    // 33792

#define KCH 32
#define NC1 (IN_DIM / KCH)    // 16
#define NC2 (HID_DIM / KCH)   // 32
#define NSTAGE 3

// smem stage layout (bytes); all offsets 16B aligned
#define A_LD 40               // fp16 elems per A row (32 data + 8 pad); 80B stride
#define A_ROWB (A_LD * 2)
#define B_LD 264              // fp16 elems per B row (256 data + 8 pad); 528B stride
#define B_ROWB (B_LD * 2)
#define AH_OFF 0
#define BH_OFF (TILE_M * A_ROWB)              // 10240
#define STAGE_BYTES (BH_OFF + KCH * B_ROWB)   // 27136
#define SMEM_TOTAL (NSTAGE * STAGE_BYTES)     // 81408 (dynamic, opt-in)

// ---------------- device scratch (referenced from DEVICE code only!) -------
__device__ int   g_topk_idx[NTOK * TOPK];
__device__ float g_topk_w[NTOK * TOPK];
__device__ int   g_counts[N_EXPERTS];
__device__ int   g_cursor[N_EXPERTS];
__device__ int   g_tile_expert[MAX_TILES];
__device__ int   g_tile_base[MAX_TILES];
__device__ int   g_num_tiles;
__device__ int   g_assign_token[PADDED];
__device__ float g_assign_w[PADDED];
__device__ int   g_token_slot[NTOK * TOPK];

__device__ __align__(16) __half g_zero[64];   // stays all-zero
__device__ __align__(16) __half g_xh[(size_t)NTOK * IN_DIM];
__device__ __align__(16) __half g_w1h[(size_t)N_EXPERTS * IN_DIM * HID_DIM];
__device__ __align__(16) __half g_w2h[(size_t)N_EXPERTS * HID_DIM * OUT_DIM];
__device__ __align__(16) __half g_hidh[(size_t)PADDED * HID_DIM];
__device__ __align__(16) float  g_expout[(size_t)PADDED * OUT_DIM];

// ---------------- helpers ----------------
__device__ __forceinline__ uint32_t cvta_s(const void* p) {
    return (uint32_t)__cvta_generic_to_shared(p);
}
__device__ __forceinline__ void cp16(uint32_t s, const void* g) {
    asm volatile("cp.async.cg.shared.global [%0], [%1], 16;" :: "r"(s), "l"(g));
}
__device__ __forceinline__ void cp_commit() { asm volatile("cp.async.commit_group;" ::: "memory"); }
__device__ __forceinline__ void cp_wait1()  { asm volatile("cp.async.wait_group 1;" ::: "memory"); }
__device__ __forceinline__ void cp_wait0()  { asm volatile("cp.async.wait_group 0;" ::: "memory"); }

__device__ __forceinline__ float gelu_exact(float v) {
    return 0.5f * v * (1.0f + erff(v * 0.70710678118654752440f));
}

// ---------------- K0: reset per-launch state ------------------------------
__global__ void zero_kernel() {
    int idx = blockIdx.x * blockDim.x + threadIdx.x;
    if (idx < PADDED) g_assign_token[idx] = -1;
    if (idx < N_EXPERTS) g_counts[idx] = 0;
    if (idx < 64) g_zero[idx] = __float2half(0.0f);
}

// ---------------- K0b: fp32 -> fp16 conversions ---------------------------
__global__ void conv_x_kernel(const float* __restrict__ src) {
    size_t i = (size_t)blockIdx.x * blockDim.x + threadIdx.x;
    if (i >= (size_t)NTOK * IN_DIM / 4) return;
    float4 v = *(const float4*)(src + i * 4);
    __half h[4];
    h[0] = __float2half(v.x); h[1] = __float2half(v.y);
    h[2] = __float2half(v.z); h[3] = __float2half(v.w);
    *(uint2*)(g_xh + i * 4) = *(uint2*)h;
}
__global__ void conv_w1_kernel(const float* __restrict__ src) {
    size_t i = (size_t)blockIdx.x * blockDim.x + threadIdx.x;
    if (i >= (size_t)N_EXPERTS * IN_DIM * HID_DIM / 4) return;
    float4 v = *(const float4*)(src + i * 4);
    __half h[4];
    h[0] = __float2half(v.x); h[1] = __float2half(v.y);
    h[2] = __float2half(v.z); h[3] = __float2half(v.w);
    *(uint2*)(g_w1h + i * 4) = *(uint2*)h;
}
__global__ void conv_w2_kernel(const float* __restrict__ src) {
    size_t i = (size_t)blockIdx.x * blockDim.x + threadIdx.x;
    if (i >= (size_t)N_EXPERTS * HID_DIM * OUT_DIM / 4) return;
    float4 v = *(const float4*)(src + i * 4);
    __half h[4];
    h[0] = __float2half(v.x); h[1] = __float2half(v.y);
    h[2] = __float2half(v.z); h[3] = __float2half(v.w);
    *(uint2*)(g_w2h + i * 4) = *(uint2*)h;
}

// ---------------- K1: gating — one warp per token -------------------------
__global__ void gating_kernel(const float* __restrict__ x,
                              const float* __restrict__ gw,
                              const float* __restrict__ gb) {
    int token = blockIdx.x * (blockDim.x >> 5) + (threadIdx.x >> 5);
    if (token >= NTOK) return;
    int lane = threadIdx.x & 31;
    float s[N_EXPERTS];
#pragma unroll
    for (int e = 0; e < N_EXPERTS; e++) s[e] = 0.0f;
    const float* xr = x + (size_t)token * IN_DIM;
    for (int i = lane; i < IN_DIM; i += 32) {
        float xv = xr[i];
        const float* g = gw + (size_t)i * N_EXPERTS;
#pragma unroll
        for (int e = 0; e < N_EXPERTS; e++) s[e] += xv * g[e];
    }
#pragma unroll
    for (int off = 16; off > 0; off >>= 1)
#pragma unroll
        for (int e = 0; e < N_EXPERTS; e++)
            s[e] += __shfl_xor_sync(0xFFFFFFFFu, s[e], off);
    if (lane == 0) {
#pragma unroll
        for (int e = 0; e < N_EXPERTS; e++) s[e] += gb[e];
        float v0 = -INFINITY; int i0 = -1;
#pragma unroll
        for (int e = 0; e < N_EXPERTS; e++)
            if (s[e] > v0) { v0 = s[e]; i0 = e; }
        float v1 = -INFINITY; int i1 = -1;
#pragma unroll
        for (int e = 0; e < N_EXPERTS; e++)
            if (e != i0 && s[e] > v1) { v1 = s[e]; i1 = e; }
        float e1 = expf(v1 - v0);
        float inv = 1.0f / (1.0f + e1);
        g_topk_idx[token * 2 + 0] = i0;
        g_topk_idx[token * 2 + 1] = i1;
        g_topk_w[token * 2 + 0] = inv;
        g_topk_w[token * 2 + 1] = e1 * inv;
        atomicAdd(&g_counts[i0], 1);
        atomicAdd(&g_counts[i1], 1);
    }
}

// ---------------- K2: setup — tile table, cursors, aux loss ---------------
__global__ void setup_kernel(float* __restrict__ out, int out_size) {
    if (threadIdx.x != 0 || blockIdx.x != 0) return;
    int nt = 0, off = 0;
    for (int e = 0; e < N_EXPERTS; e++) {
        int c = g_counts[e];
        int tiles = (c + TILE_M - 1) / TILE_M;
        g_cursor[e] = off;
        for (int i = 0; i < tiles; i++) {
            g_tile_expert[nt] = e;
            g_tile_base[nt] = off + i * TILE_M;
            nt++;
        }
        off += tiles * TILE_M;
    }
    g_num_tiles = nt;
    float aux = 0.0f;
    for (int e = 0; e < N_EXPERTS; e++) {
        float f = (float)g_counts[e] / (float)(NTOK * TOPK) - 1.0f / N_EXPERTS;
        aux += f * f;
    }
    aux *= (1.0f / N_EXPERTS);
    if (out_size > NTOK * OUT_DIM) out[(size_t)NTOK * OUT_DIM] = aux;
}

// ---------------- K3: scatter tokens to expert segments -------------------
__global__ void scatter_kernel() {
    int t = blockIdx.x * blockDim.x + threadIdx.x;
    if (t >= NTOK) return;
#pragma unroll
    for (int k = 0; k < TOPK; k++) {
        int e = g_topk_idx[t * 2 + k];
        int pos = atomicAdd(&g_cursor[e], 1);
        g_assign_token[pos] = t;
        g_assign_w[pos] = g_topk_w[t * 2 + k];
        g_token_slot[t * 2 + k] = pos;
    }
}

// ---------------- cp.async stage loaders (KCH=32, TILE_N=256, 512 thr) ----
// A: 128 rows x 32 fp16 (64B = 4 x 16B chunks); ar=tid>>2, 1 chunk each
// B: 32 rows x 256 fp16 (512B = 32 chunks); br=tid>>4, 2 chunks each
__device__ __forceinline__ void load_stage_g1(uint32_t st, int tid, const int* toks,
                                              int e, int n0, int k0) {
    int ar = tid >> 2;
    int ac = (tid & 3) * 8;
    int tok = toks[ar];
    const __half* sh = (tok >= 0) ? (g_xh + (size_t)tok * IN_DIM + k0 + ac)
                                  : (g_zero + ac);
    cp16(st + AH_OFF + ar * A_ROWB + ac * 2, sh);
    int br = tid >> 4;
    int bc = (tid & 15) * 16;
    const __half* bh = g_w1h + ((size_t)e * IN_DIM + k0 + br) * HID_DIM + n0 + bc;
    uint32_t brow = st + BH_OFF + br * B_ROWB + bc * 2;
    cp16(brow, bh);
    cp16(brow + 16, bh + 8);
}

__device__ __forceinline__ void load_stage_g2(uint32_t st, int tid, int base,
                                              int e, int n0, int k0) {
    int ar = tid >> 2;
    int ac = (tid & 3) * 8;
    const __half* sh = g_hidh + (size_t)(base + ar) * HID_DIM + k0 + ac;
    cp16(st + AH_OFF + ar * A_ROWB + ac * 2, sh);
    int br = tid >> 4;
    int bc = (tid & 15) * 16;
    const __half* bh = g_w2h + ((size_t)e * HID_DIM + k0 + br) * OUT_DIM + n0 + bc;
    uint32_t brow = st + BH_OFF + br * B_ROWB + bc * 2;
    cp16(brow, bh);
    cp16(brow + 16, bh + 8);
}

// ---------------- wmma compute for one staged chunk (K=32, 2 ksteps) ------
// 16 warps: wm=wid&1 (64 rows), wn=wid>>1 (0..7, 32 cols each)
__device__ __forceinline__ void compute_chunk(
    uint8_t* sb, int wm, int wn,
    wmma::fragment<wmma::accumulator, 16, 16, 16, float> acc[4][2]) {
    __half* Ah = (__half*)(sb + AH_OFF);
    __half* Bh = (__half*)(sb + BH_OFF);
#pragma unroll
    for (int kk = 0; kk < KCH; kk += 16) {
        wmma::fragment<wmma::matrix_a, 16, 16, 16, __half, wmma::row_major> fah[4];
        wmma::fragment<wmma::matrix_b, 16, 16, 16, __half, wmma::row_major> fbh[2];
#pragma unroll
        for (int i = 0; i < 4; i++)
            wmma::load_matrix_sync(fah[i], Ah + (wm * 64 + i * 16) * A_LD + kk, A_LD);
#pragma unroll
        for (int j = 0; j < 2; j++)
            wmma::load_matrix_sync(fbh[j], Bh + kk * B_LD + wn * 32 + j * 16, B_LD);
#pragma unroll
        for (int i = 0; i < 4; i++)
#pragma unroll
            for (int j = 0; j < 2; j++)
                wmma::mma_sync(acc[i][j], fah[i], fbh[j], acc[i][j]);
    }
}

// ---------------- K4: GEMM1  h = gelu(x_sel @ w1[e] + b1[e]) --------------
__global__ __launch_bounds__(NTHREADS) void gemm1_kernel(const float* __restrict__ b1) {
    extern __shared__ __align__(16) uint8_t sm[];
    __shared__ int toks[TILE_M];

    int tile = blockIdx.x;
    if (tile >= g_num_tiles) return;
    int e = g_tile_expert[tile];
    int base = g_tile_base[tile];
    int n0 = blockIdx.y * TILE_N;
    int tid = threadIdx.x;
    int lane = tid & 31, wid = tid >> 5;
    int wm = wid & 1, wn = wid >> 1;

    if (tid < TILE_M) toks[tid] = g_assign_token[base + tid];
    __syncthreads();

    uint32_t smb = cvta_s(sm);

    wmma::fragment<wmma::accumulator, 16, 16, 16, float> acc[4][2];
#pragma unroll
    for (int i = 0; i < 4; i++)
#pragma unroll
        for (int j = 0; j < 2; j++) wmma::fill_fragment(acc[i][j], 0.0f);

    load_stage_g1(smb + 0 * STAGE_BYTES, tid, toks, e, n0, 0);
    cp_commit();
    load_stage_g1(smb + 1 * STAGE_BYTES, tid, toks, e, n0, KCH);
    cp_commit();

    int stg = 0;
    for (int c = 0; c < NC1; c++) {
        if (c + 1 < NC1) cp_wait1(); else cp_wait0();
        __syncthreads();   // retires compute on buffer (c+2)%3 before rewrite
        if (c + 2 < NC1) {
            int ws = stg + 2; if (ws >= NSTAGE) ws -= NSTAGE;
            load_stage_g1(smb + ws * STAGE_BYTES, tid, toks, e, n0, (c + 2) * KCH);
            cp_commit();
        }
        compute_chunk(sm + stg * STAGE_BYTES, wm, wn, acc);
        if (++stg == NSTAGE) stg = 0;
    }
    __syncthreads();

    float* cpatch = (float*)sm + wid * 256;
    const float* b1e = b1 + (size_t)e * HID_DIM + n0;
#pragma unroll
    for (int i = 0; i < 4; i++)
#pragma unroll
        for (int j = 0; j < 2; j++) {
            wmma::store_matrix_sync(cpatch, acc[i][j], 16, wmma::mem_row_major);
            __syncwarp();
            int r0 = wm * 64 + i * 16;
            int c0 = wn * 32 + j * 16;
            int rr = (lane * 8) >> 4;
            int cc = (lane * 8) & 15;
            __half hbuf[8];
#pragma unroll
            for (int q = 0; q < 8; q++) {
                float v = gelu_exact(cpatch[lane * 8 + q] + b1e[c0 + cc + q]);
                hbuf[q] = __float2half(v);
            }
            size_t di = (size_t)(base + r0 + rr) * HID_DIM + n0 + c0 + cc;
            *(uint4*)(g_hidh + di) = *(uint4*)hbuf;
            __syncwarp();
        }
}

// ---------------- K5: GEMM2  expout[slot] = w * (h @ w2[e] + b2[e]) -------
__global__ __launch_bounds__(NTHREADS) void gemm2_kernel(const float* __restrict__ b2) {
    extern __shared__ __align__(16) uint8_t sm[];
    __shared__ float wts[TILE_M];

    int tile = blockIdx.x;
    if (tile >= g_num_tiles) return;
    int e = g_tile_expert[tile];
    int base = g_tile_base[tile];
    int n0 = blockIdx.y * TILE_N;
    int tid = threadIdx.x;
    int lane = tid & 31, wid = tid >> 5;
    int wm = wid & 1, wn = wid >> 1;

    if (tid < TILE_M) wts[tid] = g_assign_w[base + tid];
    __syncthreads();

    uint32_t smb = cvta_s(sm);

    wmma::fragment<wmma::accumulator, 16, 16, 16, float> acc[4][2];
#pragma unroll
    for (int i = 0; i < 4; i++)
#pragma unroll
        for (int j = 0; j < 2; j++) wmma::fill_fragment(acc[i][j], 0.0f);

    load_stage_g2(smb + 0 * STAGE_BYTES, tid, base, e, n0, 0);
    cp_commit();
    load_stage_g2(smb + 1 * STAGE_BYTES, tid, base, e, n0, KCH);
    cp_commit();

    int stg = 0;
    for (int c = 0; c < NC2; c++) {
        if (c + 1 < NC2) cp_wait1(); else cp_wait0();
        __syncthreads();
        if (c + 2 < NC2) {
            int ws = stg + 2; if (ws >= NSTAGE) ws -= NSTAGE;
            load_stage_g2(smb + ws * STAGE_BYTES, tid, base, e, n0, (c + 2) * KCH);
            cp_commit();
        }
        compute_chunk(sm + stg * STAGE_BYTES, wm, wn, acc);
        if (++stg == NSTAGE) stg = 0;
    }
    __syncthreads();

    float* cpatch = (float*)sm + wid * 256;
    const float* b2e = b2 + (size_t)e * OUT_DIM + n0;
#pragma unroll
    for (int i = 0; i < 4; i++)
#pragma unroll
        for (int j = 0; j < 2; j++) {
            wmma::store_matrix_sync(cpatch, acc[i][j], 16, wmma::mem_row_major);
            __syncwarp();
            int r0 = wm * 64 + i * 16;
            int c0 = wn * 32 + j * 16;
            int rr = (lane * 8) >> 4;
            int cc = (lane * 8) & 15;
            float wt = wts[r0 + rr];
            size_t di = (size_t)(base + r0 + rr) * OUT_DIM + n0 + c0 + cc;
            float4 v;
            v.x = (cpatch[lane * 8 + 0] + b2e[c0 + cc + 0]) * wt;
            v.y = (cpatch[lane * 8 + 1] + b2e[c0 + cc + 1]) * wt;
            v.z = (cpatch[lane * 8 + 2] + b2e[c0 + cc + 2]) * wt;
            v.w = (cpatch[lane * 8 + 3] + b2e[c0 + cc + 3]) * wt;
            *(float4*)(g_expout + di) = v;
            float4 v2;
            v2.x = (cpatch[lane * 8 + 4] + b2e[c0 + cc + 4]) * wt;
            v2.y = (cpatch[lane * 8 + 5] + b2e[c0 + cc + 5]) * wt;
            v2.z = (cpatch[lane * 8 + 6] + b2e[c0 + cc + 6]) * wt;
            v2.w = (cpatch[lane * 8 + 7] + b2e[c0 + cc + 7]) * wt;
            *(float4*)(g_expout + di + 4) = v2;
            __syncwarp();
        }
}

// ---------------- K6: combine the two expert slots per token --------------
__global__ void combine_kernel(float* __restrict__ out) {
    int idx = blockIdx.x * blockDim.x + threadIdx.x;   // NTOK * 128
    int t = idx >> 7, q = (idx & 127) * 4;
    if (t >= NTOK) return;
    int s0 = g_token_slot[t * 2 + 0];
    int s1 = g_token_slot[t * 2 + 1];
    float4 v0 = *(const float4*)(g_expout + (size_t)s0 * OUT_DIM + q);
    float4 v1 = *(const float4*)(g_expout + (size_t)s1 * OUT_DIM + q);
    float4 r;
    r.x = v0.x + v1.x; r.y = v0.y + v1.y; r.z = v0.z + v1.z; r.w = v0.w + v1.w;
    *(float4*)(out + (size_t)t * OUT_DIM + q) = r;
}

// ---------------- launch ---------------------------------------------------
extern "C" void kernel_launch(void* const* d_in, const int* in_sizes, int n_in,
                              void* d_out, int out_size) {
    const float* x      = (const float*)d_in[0];
    const float* gate_w = (const float*)d_in[1];
    const float* gate_b = (const float*)d_in[2];
    const float* w1     = (const float*)d_in[3];
    const float* b1     = (const float*)d_in[4];
    const float* w2     = (const float*)d_in[5];
    const float* b2     = (const float*)d_in[6];
    float* out = (float*)d_out;

    cudaFuncSetAttribute(gemm1_kernel, cudaFuncAttributeMaxDynamicSharedMemorySize, SMEM_TOTAL);
    cudaFuncSetAttribute(gemm2_kernel, cudaFuncAttributeMaxDynamicSharedMemorySize, SMEM_TOTAL);

    zero_kernel<<<(PADDED + 255) / 256, 256>>>();
    {
        size_t nx = (size_t)NTOK * IN_DIM / 4;
        conv_x_kernel<<<(int)((nx + 255) / 256), 256>>>(x);
        size_t n1 = (size_t)N_EXPERTS * IN_DIM * HID_DIM / 4;
        conv_w1_kernel<<<(int)((n1 + 255) / 256), 256>>>(w1);
        size_t n2 = (size_t)N_EXPERTS * HID_DIM * OUT_DIM / 4;
        conv_w2_kernel<<<(int)((n2 + 255) / 256), 256>>>(w2);
    }
    gating_kernel<<<NTOK / 8, 256>>>(x, gate_w, gate_b);
    setup_kernel<<<1, 32>>>(out, out_size);
    scatter_kernel<<<NTOK / 256, 256>>>();
    {
        dim3 grid(MAX_TILES, HID_DIM / TILE_N);   // 264 x 4
        gemm1_kernel<<<grid, NTHREADS, SMEM_TOTAL>>>(b1);
    }
    {
        dim3 grid(MAX_TILES, OUT_DIM / TILE_N);   // 264 x 2
        gemm2_kernel<<<grid, NTHREADS, SMEM_TOTAL>>>(b2);
    }
    combine_kernel<<<(NTOK * 128) / 256, 256>>>(out);
}

// round 17
// speedup vs baseline: 1.0993x; 1.0993x over previous
#include <cuda_runtime.h>
#include <cuda_fp16.h>
#include <mma.h>
#include <math.h>
#include <stdint.h>

using namespace nvcuda;

#define N_EXPERTS 8
#define TOPK      2
#define IN_DIM    512
#define HID_DIM   1024
#define OUT_DIM   512
#define NTOK      16384

#define TILE_M 128
#define TILE_N 128
#define MAX_TILES ((NTOK * TOPK) / TILE_M + N_EXPERTS)   // 264
#define PADDED    (MAX_TILES * TILE_M)                    // 33792

#define KCH 32
#define NC1 (IN_DIM / KCH)    // 16
#define NC2 (HID_DIM / KCH)   // 32
#define NSTAGE 4

// smem stage layout (bytes); all offsets 16B aligned
#define A_LD 40               // fp16 elems per A row (32 data + 8 pad); 80B stride
#define A_ROWB (A_LD * 2)
#define B_LD 136              // fp16 elems per B row (128 data + 8 pad); 272B stride
#define B_ROWB (B_LD * 2)
#define AH_OFF 0
#define BH_OFF (TILE_M * A_ROWB)              // 10240
#define STAGE_BYTES (BH_OFF + KCH * B_ROWB)   // 18944
#define SMEM_TOTAL (NSTAGE * STAGE_BYTES)     // 75776 (dynamic, opt-in)

// conversion ranges (in float4 units)
#define NX4 ((size_t)NTOK * IN_DIM / 4)
#define NW14 ((size_t)N_EXPERTS * IN_DIM * HID_DIM / 4)
#define NW24 ((size_t)N_EXPERTS * HID_DIM * OUT_DIM / 4)

// ---------------- device scratch (referenced from DEVICE code only!) -------
__device__ int   g_topk_idx[NTOK * TOPK];
__device__ float g_topk_w[NTOK * TOPK];
__device__ int   g_counts[N_EXPERTS];
__device__ int   g_cursor[N_EXPERTS];
__device__ int   g_tile_expert[MAX_TILES];
__device__ int   g_tile_base[MAX_TILES];
__device__ int   g_num_tiles;
__device__ int   g_assign_token[PADDED];
__device__ float g_assign_w[PADDED];
__device__ int   g_token_slot[NTOK * TOPK];

__device__ __align__(16) __half g_zero[64];   // stays all-zero
__device__ __align__(16) __half g_xh[(size_t)NTOK * IN_DIM];
__device__ __align__(16) __half g_w1h[(size_t)N_EXPERTS * IN_DIM * HID_DIM];
__device__ __align__(16) __half g_w2h[(size_t)N_EXPERTS * HID_DIM * OUT_DIM];
__device__ __align__(16) __half g_hidh[(size_t)PADDED * HID_DIM];
__device__ __align__(16) float  g_expout[(size_t)PADDED * OUT_DIM];

// ---------------- helpers ----------------
__device__ __forceinline__ uint32_t cvta_s(const void* p) {
    return (uint32_t)__cvta_generic_to_shared(p);
}
__device__ __forceinline__ void cp16(uint32_t s, const void* g) {
    asm volatile("cp.async.cg.shared.global [%0], [%1], 16;" :: "r"(s), "l"(g));
}
__device__ __forceinline__ void cp_commit() { asm volatile("cp.async.commit_group;" ::: "memory"); }
__device__ __forceinline__ void cp_wait2()  { asm volatile("cp.async.wait_group 2;" ::: "memory"); }
__device__ __forceinline__ void cp_wait1()  { asm volatile("cp.async.wait_group 1;" ::: "memory"); }
__device__ __forceinline__ void cp_wait0()  { asm volatile("cp.async.wait_group 0;" ::: "memory"); }

__device__ __forceinline__ float gelu_exact(float v) {
    return 0.5f * v * (1.0f + erff(v * 0.70710678118654752440f));
}

// ---------------- K0: reset per-launch state ------------------------------
__global__ void zero_kernel() {
    int idx = blockIdx.x * blockDim.x + threadIdx.x;
    if (idx < PADDED) g_assign_token[idx] = -1;
    if (idx < N_EXPERTS) g_counts[idx] = 0;
    if (idx < 64) g_zero[idx] = __float2half(0.0f);
}

// ---------------- K0b: fused fp32 -> fp16 conversion (x | w1 | w2) --------
__global__ void conv_all_kernel(const float* __restrict__ x,
                                const float* __restrict__ w1,
                                const float* __restrict__ w2) {
    size_t i = (size_t)blockIdx.x * blockDim.x + threadIdx.x;
    const float* src;
    __half* dst;
    size_t off;
    if (i < NX4) {
        src = x; dst = g_xh; off = i;
    } else if (i < NX4 + NW14) {
        src = w1; dst = g_w1h; off = i - NX4;
    } else if (i < NX4 + NW14 + NW24) {
        src = w2; dst = g_w2h; off = i - NX4 - NW14;
    } else {
        return;
    }
    float4 v = *(const float4*)(src + off * 4);
    __half h[4];
    h[0] = __float2half(v.x); h[1] = __float2half(v.y);
    h[2] = __float2half(v.z); h[3] = __float2half(v.w);
    *(uint2*)(dst + off * 4) = *(uint2*)h;
}

// ---------------- K1: gating — one warp per token -------------------------
__global__ void gating_kernel(const float* __restrict__ x,
                              const float* __restrict__ gw,
                              const float* __restrict__ gb) {
    int token = blockIdx.x * (blockDim.x >> 5) + (threadIdx.x >> 5);
    if (token >= NTOK) return;
    int lane = threadIdx.x & 31;
    float s[N_EXPERTS];
#pragma unroll
    for (int e = 0; e < N_EXPERTS; e++) s[e] = 0.0f;
    const float* xr = x + (size_t)token * IN_DIM;
    for (int i = lane; i < IN_DIM; i += 32) {
        float xv = xr[i];
        const float* g = gw + (size_t)i * N_EXPERTS;
#pragma unroll
        for (int e = 0; e < N_EXPERTS; e++) s[e] += xv * g[e];
    }
#pragma unroll
    for (int off = 16; off > 0; off >>= 1)
#pragma unroll
        for (int e = 0; e < N_EXPERTS; e++)
            s[e] += __shfl_xor_sync(0xFFFFFFFFu, s[e], off);
    if (lane == 0) {
#pragma unroll
        for (int e = 0; e < N_EXPERTS; e++) s[e] += gb[e];
        float v0 = -INFINITY; int i0 = -1;
#pragma unroll
        for (int e = 0; e < N_EXPERTS; e++)
            if (s[e] > v0) { v0 = s[e]; i0 = e; }
        float v1 = -INFINITY; int i1 = -1;
#pragma unroll
        for (int e = 0; e < N_EXPERTS; e++)
            if (e != i0 && s[e] > v1) { v1 = s[e]; i1 = e; }
        float e1 = expf(v1 - v0);
        float inv = 1.0f / (1.0f + e1);
        g_topk_idx[token * 2 + 0] = i0;
        g_topk_idx[token * 2 + 1] = i1;
        g_topk_w[token * 2 + 0] = inv;
        g_topk_w[token * 2 + 1] = e1 * inv;
        atomicAdd(&g_counts[i0], 1);
        atomicAdd(&g_counts[i1], 1);
    }
}

// ---------------- K2: setup — tile table, cursors, aux loss ---------------
__global__ void setup_kernel(float* __restrict__ out, int out_size) {
    if (threadIdx.x != 0 || blockIdx.x != 0) return;
    int nt = 0, off = 0;
    for (int e = 0; e < N_EXPERTS; e++) {
        int c = g_counts[e];
        int tiles = (c + TILE_M - 1) / TILE_M;
        g_cursor[e] = off;
        for (int i = 0; i < tiles; i++) {
            g_tile_expert[nt] = e;
            g_tile_base[nt] = off + i * TILE_M;
            nt++;
        }
        off += tiles * TILE_M;
    }
    g_num_tiles = nt;
    float aux = 0.0f;
    for (int e = 0; e < N_EXPERTS; e++) {
        float f = (float)g_counts[e] / (float)(NTOK * TOPK) - 1.0f / N_EXPERTS;
        aux += f * f;
    }
    aux *= (1.0f / N_EXPERTS);
    if (out_size > NTOK * OUT_DIM) out[(size_t)NTOK * OUT_DIM] = aux;
}

// ---------------- K3: scatter tokens to expert segments -------------------
__global__ void scatter_kernel() {
    int t = blockIdx.x * blockDim.x + threadIdx.x;
    if (t >= NTOK) return;
#pragma unroll
    for (int k = 0; k < TOPK; k++) {
        int e = g_topk_idx[t * 2 + k];
        int pos = atomicAdd(&g_cursor[e], 1);
        g_assign_token[pos] = t;
        g_assign_w[pos] = g_topk_w[t * 2 + k];
        g_token_slot[t * 2 + k] = pos;
    }
}

// ---------------- cp.async stage loaders (KCH=32) ----------------
__device__ __forceinline__ void load_stage_g1(uint32_t st, int tid, const int* toks,
                                              int e, int n0, int k0) {
    int ar = tid >> 1;
    int ac = (tid & 1) * 16;
    int tok = toks[ar];
    const __half* sh = (tok >= 0) ? (g_xh + (size_t)tok * IN_DIM + k0 + ac)
                                  : (g_zero + ac);
    uint32_t arow = st + AH_OFF + ar * A_ROWB + ac * 2;
    cp16(arow, sh);
    cp16(arow + 16, sh + 8);
    int br = tid >> 3;
    int bc = (tid & 7) * 16;
    const __half* bh = g_w1h + ((size_t)e * IN_DIM + k0 + br) * HID_DIM + n0 + bc;
    uint32_t brow = st + BH_OFF + br * B_ROWB + bc * 2;
    cp16(brow, bh);
    cp16(brow + 16, bh + 8);
}

__device__ __forceinline__ void load_stage_g2(uint32_t st, int tid, int base,
                                              int e, int n0, int k0) {
    int ar = tid >> 1;
    int ac = (tid & 1) * 16;
    const __half* sh = g_hidh + (size_t)(base + ar) * HID_DIM + k0 + ac;
    uint32_t arow = st + AH_OFF + ar * A_ROWB + ac * 2;
    cp16(arow, sh);
    cp16(arow + 16, sh + 8);
    int br = tid >> 3;
    int bc = (tid & 7) * 16;
    const __half* bh = g_w2h + ((size_t)e * HID_DIM + k0 + br) * OUT_DIM + n0 + bc;
    uint32_t brow = st + BH_OFF + br * B_ROWB + bc * 2;
    cp16(brow, bh);
    cp16(brow + 16, bh + 8);
}

// ---------------- wmma compute for one staged chunk (K=32, 2 ksteps) ------
__device__ __forceinline__ void compute_chunk(
    uint8_t* sb, int wm, int wn,
    wmma::fragment<wmma::accumulator, 16, 16, 16, float> acc[4][2]) {
    __half* Ah = (__half*)(sb + AH_OFF);
    __half* Bh = (__half*)(sb + BH_OFF);
#pragma unroll
    for (int kk = 0; kk < KCH; kk += 16) {
        wmma::fragment<wmma::matrix_a, 16, 16, 16, __half, wmma::row_major> fah[4];
        wmma::fragment<wmma::matrix_b, 16, 16, 16, __half, wmma::row_major> fbh[2];
#pragma unroll
        for (int i = 0; i < 4; i++)
            wmma::load_matrix_sync(fah[i], Ah + (wm * 64 + i * 16) * A_LD + kk, A_LD);
#pragma unroll
        for (int j = 0; j < 2; j++)
            wmma::load_matrix_sync(fbh[j], Bh + kk * B_LD + wn * 32 + j * 16, B_LD);
#pragma unroll
        for (int i = 0; i < 4; i++)
#pragma unroll
            for (int j = 0; j < 2; j++)
                wmma::mma_sync(acc[i][j], fah[i], fbh[j], acc[i][j]);
    }
}

// ---------------- K4: GEMM1  h = gelu(x_sel @ w1[e] + b1[e]) --------------
__global__ __launch_bounds__(256) void gemm1_kernel(const float* __restrict__ b1) {
    extern __shared__ __align__(16) uint8_t sm[];
    __shared__ int toks[TILE_M];

    int tile = blockIdx.x;
    if (tile >= g_num_tiles) return;
    int e = g_tile_expert[tile];
    int base = g_tile_base[tile];
    int n0 = blockIdx.y * TILE_N;
    int tid = threadIdx.x;
    int lane = tid & 31, wid = tid >> 5;
    int wm = wid & 1, wn = wid >> 1;

    if (tid < TILE_M) toks[tid] = g_assign_token[base + tid];
    __syncthreads();

    uint32_t smb = cvta_s(sm);

    wmma::fragment<wmma::accumulator, 16, 16, 16, float> acc[4][2];
#pragma unroll
    for (int i = 0; i < 4; i++)
#pragma unroll
        for (int j = 0; j < 2; j++) wmma::fill_fragment(acc[i][j], 0.0f);

    // 4-stage prologue: three chunks in flight
    load_stage_g1(smb + 0 * STAGE_BYTES, tid, toks, e, n0, 0);
    cp_commit();
    load_stage_g1(smb + 1 * STAGE_BYTES, tid, toks, e, n0, KCH);
    cp_commit();
    load_stage_g1(smb + 2 * STAGE_BYTES, tid, toks, e, n0, 2 * KCH);
    cp_commit();

    int stg = 0;
    for (int c = 0; c < NC1; c++) {
        int remaining = NC1 - c;
        if (remaining >= 3) cp_wait2();
        else if (remaining == 2) cp_wait1();
        else cp_wait0();
        __syncthreads();   // retires compute on buffer (c+3)%4 == (c-1)%4 before rewrite
        if (c + 3 < NC1) {
            int ws = stg + 3; if (ws >= NSTAGE) ws -= NSTAGE;
            load_stage_g1(smb + ws * STAGE_BYTES, tid, toks, e, n0, (c + 3) * KCH);
            cp_commit();
        }
        compute_chunk(sm + stg * STAGE_BYTES, wm, wn, acc);
        if (++stg == NSTAGE) stg = 0;
    }
    __syncthreads();

    float* cpatch = (float*)sm + wid * 256;
    const float* b1e = b1 + (size_t)e * HID_DIM + n0;
#pragma unroll
    for (int i = 0; i < 4; i++)
#pragma unroll
        for (int j = 0; j < 2; j++) {
            wmma::store_matrix_sync(cpatch, acc[i][j], 16, wmma::mem_row_major);
            __syncwarp();
            int r0 = wm * 64 + i * 16;
            int c0 = wn * 32 + j * 16;
            int rr = (lane * 8) >> 4;
            int cc = (lane * 8) & 15;
            __half hbuf[8];
#pragma unroll
            for (int q = 0; q < 8; q++) {
                float v = gelu_exact(cpatch[lane * 8 + q] + b1e[c0 + cc + q]);
                hbuf[q] = __float2half(v);
            }
            size_t di = (size_t)(base + r0 + rr) * HID_DIM + n0 + c0 + cc;
            *(uint4*)(g_hidh + di) = *(uint4*)hbuf;
            __syncwarp();
        }
}

// ---------------- K5: GEMM2  expout[slot] = w * (h @ w2[e] + b2[e]) -------
__global__ __launch_bounds__(256) void gemm2_kernel(const float* __restrict__ b2) {
    extern __shared__ __align__(16) uint8_t sm[];
    __shared__ float wts[TILE_M];

    int tile = blockIdx.x;
    if (tile >= g_num_tiles) return;
    int e = g_tile_expert[tile];
    int base = g_tile_base[tile];
    int n0 = blockIdx.y * TILE_N;
    int tid = threadIdx.x;
    int lane = tid & 31, wid = tid >> 5;
    int wm = wid & 1, wn = wid >> 1;

    if (tid < TILE_M) wts[tid] = g_assign_w[base + tid];
    __syncthreads();

    uint32_t smb = cvta_s(sm);

    wmma::fragment<wmma::accumulator, 16, 16, 16, float> acc[4][2];
#pragma unroll
    for (int i = 0; i < 4; i++)
#pragma unroll
        for (int j = 0; j < 2; j++) wmma::fill_fragment(acc[i][j], 0.0f);

    load_stage_g2(smb + 0 * STAGE_BYTES, tid, base, e, n0, 0);
    cp_commit();
    load_stage_g2(smb + 1 * STAGE_BYTES, tid, base, e, n0, KCH);
    cp_commit();
    load_stage_g2(smb + 2 * STAGE_BYTES, tid, base, e, n0, 2 * KCH);
    cp_commit();

    int stg = 0;
    for (int c = 0; c < NC2; c++) {
        int remaining = NC2 - c;
        if (remaining >= 3) cp_wait2();
        else if (remaining == 2) cp_wait1();
        else cp_wait0();
        __syncthreads();
        if (c + 3 < NC2) {
            int ws = stg + 3; if (ws >= NSTAGE) ws -= NSTAGE;
            load_stage_g2(smb + ws * STAGE_BYTES, tid, base, e, n0, (c + 3) * KCH);
            cp_commit();
        }
        compute_chunk(sm + stg * STAGE_BYTES, wm, wn, acc);
        if (++stg == NSTAGE) stg = 0;
    }
    __syncthreads();

    float* cpatch = (float*)sm + wid * 256;
    const float* b2e = b2 + (size_t)e * OUT_DIM + n0;
#pragma unroll
    for (int i = 0; i < 4; i++)
#pragma unroll
        for (int j = 0; j < 2; j++) {
            wmma::store_matrix_sync(cpatch, acc[i][j], 16, wmma::mem_row_major);
            __syncwarp();
            int r0 = wm * 64 + i * 16;
            int c0 = wn * 32 + j * 16;
            int rr = (lane * 8) >> 4;
            int cc = (lane * 8) & 15;
            float wt = wts[r0 + rr];
            size_t di = (size_t)(base + r0 + rr) * OUT_DIM + n0 + c0 + cc;
            float4 v;
            v.x = (cpatch[lane * 8 + 0] + b2e[c0 + cc + 0]) * wt;
            v.y = (cpatch[lane * 8 + 1] + b2e[c0 + cc + 1]) * wt;
            v.z = (cpatch[lane * 8 + 2] + b2e[c0 + cc + 2]) * wt;
            v.w = (cpatch[lane * 8 + 3] + b2e[c0 + cc + 3]) * wt;
            *(float4*)(g_expout + di) = v;
            float4 v2;
            v2.x = (cpatch[lane * 8 + 4] + b2e[c0 + cc + 4]) * wt;
            v2.y = (cpatch[lane * 8 + 5] + b2e[c0 + cc + 5]) * wt;
            v2.z = (cpatch[lane * 8 + 6] + b2e[c0 + cc + 6]) * wt;
            v2.w = (cpatch[lane * 8 + 7] + b2e[c0 + cc + 7]) * wt;
            *(float4*)(g_expout + di + 4) = v2;
            __syncwarp();
        }
}

// ---------------- K6: combine the two expert slots per token --------------
__global__ void combine_kernel(float* __restrict__ out) {
    int idx = blockIdx.x * blockDim.x + threadIdx.x;   // NTOK * 128
    int t = idx >> 7, q = (idx & 127) * 4;
    if (t >= NTOK) return;
    int s0 = g_token_slot[t * 2 + 0];
    int s1 = g_token_slot[t * 2 + 1];
    float4 v0 = *(const float4*)(g_expout + (size_t)s0 * OUT_DIM + q);
    float4 v1 = *(const float4*)(g_expout + (size_t)s1 * OUT_DIM + q);
    float4 r;
    r.x = v0.x + v1.x; r.y = v0.y + v1.y; r.z = v0.z + v1.z; r.w = v0.w + v1.w;
    *(float4*)(out + (size_t)t * OUT_DIM + q) = r;
}

// ---------------- launch ---------------------------------------------------
extern "C" void kernel_launch(void* const* d_in, const int* in_sizes, int n_in,
                              void* d_out, int out_size) {
    const float* x      = (const float*)d_in[0];
    const float* gate_w = (const float*)d_in[1];
    const float* gate_b = (const float*)d_in[2];
    const float* w1     = (const float*)d_in[3];
    const float* b1     = (const float*)d_in[4];
    const float* w2     = (const float*)d_in[5];
    const float* b2     = (const float*)d_in[6];
    float* out = (float*)d_out;

    cudaFuncSetAttribute(gemm1_kernel, cudaFuncAttributeMaxDynamicSharedMemorySize, SMEM_TOTAL);
    cudaFuncSetAttribute(gemm2_kernel, cudaFuncAttributeMaxDynamicSharedMemorySize, SMEM_TOTAL);

    zero_kernel<<<(PADDED + 255) / 256, 256>>>();
    {
        size_t ntotal = NX4 + NW14 + NW24;
        conv_all_kernel<<<(int)((ntotal + 255) / 256), 256>>>(x, w1, w2);
    }
    gating_kernel<<<NTOK / 8, 256>>>(x, gate_w, gate_b);
    setup_kernel<<<1, 32>>>(out, out_size);
    scatter_kernel<<<NTOK / 256, 256>>>();
    {
        dim3 grid(MAX_TILES, HID_DIM / TILE_N);   // 264 x 8
        gemm1_kernel<<<grid, 256, SMEM_TOTAL>>>(b1);
    }
    {
        dim3 grid(MAX_TILES, OUT_DIM / TILE_N);   // 264 x 4
        gemm2_kernel<<<grid, 256, SMEM_TOTAL>>>(b2);
    }
    combine_kernel<<<(NTOK * 128) / 256, 256>>>(out);
}